// round 4
// baseline (speedup 1.0000x reference)
#include <cuda_runtime.h>

#define N_NODES  100000
#define N_EDGES  3200000
#define N_GRAPHS 256

static __device__ int   g_is64;
static __device__ int   g_src[N_EDGES];
static __device__ int   g_dst[N_EDGES];
static __device__ int   g_ssrc[N_EDGES];      // src sorted by dst (CSR payload)
static __device__ int   g_cnt[N_NODES];
static __device__ int   g_rowptr[N_NODES + 1];
static __device__ int   g_cursor[N_NODES];
static __device__ float g_dinv[N_NODES];
static __device__ float g_selfw[N_NODES];
static __device__ __align__(16) float g_bufA[(size_t)N_NODES * 128];
static __device__ __align__(16) float g_bufB[(size_t)N_NODES * 128];
static __device__ float g_psum[N_GRAPHS * 64];
static __device__ int   g_pcnt[N_GRAPHS];
static __device__ int   g_bsum[128];
static __device__ int   g_boff[128];

static constexpr int SCAN_CHUNK  = 1024;
static constexpr int SCAN_BLOCKS = (N_NODES + SCAN_CHUNK - 1) / SCAN_CHUNK;

// ---------------------------------------------------------------- utilities

__global__ void zero_kernel() {
    int i = blockIdx.x * blockDim.x + threadIdx.x;
    if (i < N_NODES)      g_cnt[i]  = 0;
    if (i < N_GRAPHS*64)  g_psum[i] = 0.f;
    if (i < N_GRAPHS)     g_pcnt[i] = 0;
}

// Detect whether edge_index arrived as int64 (odd int32 words all zero) or int32.
__global__ void detect_kernel(const int* __restrict__ ei32) {
    if (threadIdx.x == 0 && blockIdx.x == 0) {
        int allz = 1;
        for (int i = 1; i < 256; i += 2) allz &= (ei32[i] == 0);
        g_is64 = allz;
    }
}

__global__ void convert_kernel(const void* __restrict__ eidx) {
    int e = blockIdx.x * blockDim.x + threadIdx.x;
    if (e >= N_EDGES) return;
    int s, d;
    if (g_is64) {
        const long long* p = (const long long*)eidx;
        s = (int)p[e];
        d = (int)p[(size_t)N_EDGES + e];
    } else {
        const int* p = (const int*)eidx;
        s = p[e];
        d = p[N_EDGES + e];
    }
    g_src[e] = s;
    g_dst[e] = d;
    atomicAdd(&g_cnt[d], 1);
}

// ---------------------------------------------------------------- prefix scan

__global__ void scan1_kernel() {
    __shared__ int s[SCAN_CHUNK];
    int tid = threadIdx.x;
    int i = blockIdx.x * SCAN_CHUNK + tid;
    int v = (i < N_NODES) ? g_cnt[i] : 0;
    s[tid] = v;
    __syncthreads();
    for (int off = 1; off < SCAN_CHUNK; off <<= 1) {
        int t = (tid >= off) ? s[tid - off] : 0;
        __syncthreads();
        s[tid] += t;
        __syncthreads();
    }
    if (i < N_NODES) g_rowptr[i] = s[tid] - v;   // exclusive, pre-offset
    if (tid == SCAN_CHUNK - 1) g_bsum[blockIdx.x] = s[tid];
}

__global__ void scan2_kernel() {
    if (threadIdx.x == 0) {
        int run = 0;
        for (int b = 0; b < SCAN_BLOCKS; b++) { g_boff[b] = run; run += g_bsum[b]; }
    }
}

__global__ void scan3_kernel() {
    int i = blockIdx.x * blockDim.x + threadIdx.x;
    if (i > N_NODES) return;
    if (i == N_NODES) { g_rowptr[N_NODES] = N_EDGES; return; }
    int rp = g_rowptr[i] + g_boff[i / SCAN_CHUNK];
    g_rowptr[i] = rp;
    g_cursor[i] = rp;
    float deg = (float)g_cnt[i] + 1.0f;
    g_dinv[i]  = rsqrtf(deg);
    g_selfw[i] = 1.0f / deg;
}

__global__ void fill_kernel() {
    int e = blockIdx.x * blockDim.x + threadIdx.x;
    if (e >= N_EDGES) return;
    int d = g_dst[e];
    int slot = atomicAdd(&g_cursor[d], 1);
    g_ssrc[slot] = g_src[e];
}

// ---------------------------------------------------------------- aggregation

// F=8 aggregation of raw x into bufA. One warp per node, edge-parallel lanes,
// 8 register accumulators, butterfly reduce, lane 0 adds self-loop + stores.
__global__ void aggX_kernel(const float* __restrict__ x) {
    int w = (blockIdx.x * blockDim.x + threadIdx.x) >> 5;
    if (w >= N_NODES) return;
    int lane = threadIdx.x & 31;
    float dv = g_dinv[w];
    int beg = g_rowptr[w], end = g_rowptr[w + 1];
    float a0=0,a1=0,a2=0,a3=0,a4=0,a5=0,a6=0,a7=0;
    for (int e = beg + lane; e < end; e += 32) {
        int s = g_ssrc[e];
        float nrm = g_dinv[s] * dv;
        const float4* xp = (const float4*)(x + (size_t)s * 8);
        float4 u = xp[0], v = xp[1];
        a0 = fmaf(nrm, u.x, a0); a1 = fmaf(nrm, u.y, a1);
        a2 = fmaf(nrm, u.z, a2); a3 = fmaf(nrm, u.w, a3);
        a4 = fmaf(nrm, v.x, a4); a5 = fmaf(nrm, v.y, a5);
        a6 = fmaf(nrm, v.z, a6); a7 = fmaf(nrm, v.w, a7);
    }
    #pragma unroll
    for (int off = 16; off; off >>= 1) {
        a0 += __shfl_xor_sync(0xffffffffu, a0, off);
        a1 += __shfl_xor_sync(0xffffffffu, a1, off);
        a2 += __shfl_xor_sync(0xffffffffu, a2, off);
        a3 += __shfl_xor_sync(0xffffffffu, a3, off);
        a4 += __shfl_xor_sync(0xffffffffu, a4, off);
        a5 += __shfl_xor_sync(0xffffffffu, a5, off);
        a6 += __shfl_xor_sync(0xffffffffu, a6, off);
        a7 += __shfl_xor_sync(0xffffffffu, a7, off);
    }
    if (lane == 0) {
        float sw = g_selfw[w];
        const float4* xp = (const float4*)(x + (size_t)w * 8);
        float4 u = xp[0], v = xp[1];
        float4 o0 = make_float4(a0 + sw*u.x, a1 + sw*u.y, a2 + sw*u.z, a3 + sw*u.w);
        float4 o1 = make_float4(a4 + sw*v.x, a5 + sw*v.y, a6 + sw*v.z, a7 + sw*v.w);
        float4* op = (float4*)(g_bufA + (size_t)w * 8);
        op[0] = o0; op[1] = o1;
    }
}

// F=64 aggregation. One warp per dst node, lane owns a float2 column pair.
// 4-way edge unroll for memory-level parallelism (L2-hit latency hiding).
template <bool BIAS_RELU>
__global__ void agg64_kernel(int inB, int outB, const float* __restrict__ bias) {
    int w = (blockIdx.x * blockDim.x + threadIdx.x) >> 5;
    if (w >= N_NODES) return;
    int lane = threadIdx.x & 31;
    int c = lane * 2;
    const float* __restrict__ in  = inB  ? g_bufB : g_bufA;
    float*       __restrict__ out = outB ? g_bufB : g_bufA;
    float dv = g_dinv[w];
    int e = g_rowptr[w], end = g_rowptr[w + 1];
    float ax0=0, ay0=0, ax1=0, ay1=0, ax2=0, ay2=0, ax3=0, ay3=0;
    for (; e + 4 <= end; e += 4) {
        int s0 = g_ssrc[e+0], s1 = g_ssrc[e+1], s2 = g_ssrc[e+2], s3 = g_ssrc[e+3];
        float n0 = g_dinv[s0]*dv, n1 = g_dinv[s1]*dv, n2 = g_dinv[s2]*dv, n3 = g_dinv[s3]*dv;
        float2 v0 = *(const float2*)(in + (size_t)s0*64 + c);
        float2 v1 = *(const float2*)(in + (size_t)s1*64 + c);
        float2 v2 = *(const float2*)(in + (size_t)s2*64 + c);
        float2 v3 = *(const float2*)(in + (size_t)s3*64 + c);
        ax0 = fmaf(n0, v0.x, ax0); ay0 = fmaf(n0, v0.y, ay0);
        ax1 = fmaf(n1, v1.x, ax1); ay1 = fmaf(n1, v1.y, ay1);
        ax2 = fmaf(n2, v2.x, ax2); ay2 = fmaf(n2, v2.y, ay2);
        ax3 = fmaf(n3, v3.x, ax3); ay3 = fmaf(n3, v3.y, ay3);
    }
    for (; e < end; e++) {
        int s = g_ssrc[e];
        float nn = g_dinv[s] * dv;
        float2 v = *(const float2*)(in + (size_t)s*64 + c);
        ax0 = fmaf(nn, v.x, ax0); ay0 = fmaf(nn, v.y, ay0);
    }
    float sw = g_selfw[w];
    float2 sv = *(const float2*)(in + (size_t)w*64 + c);
    float ox = (ax0 + ax1) + (ax2 + ax3) + sw * sv.x;
    float oy = (ay0 + ay1) + (ay2 + ay3) + sw * sv.y;
    if (BIAS_RELU) {
        ox = fmaxf(ox + bias[c],     0.f);
        oy = fmaxf(oy + bias[c + 1], 0.f);
    }
    *(float2*)(out + (size_t)w*64 + c) = make_float2(ox, oy);
}

// ---------------------------------------------------------------- GEMM

// Node-parallel GEMM: block of 256 threads; W staged in smem; each thread
// computes CPT contiguous output columns for one node.
template <int IN, int OUT, int CPT, bool ACT>
__global__ void gemm_kernel(int inB, const float* __restrict__ W,
                            const float* __restrict__ bias, int outB) {
    constexpr int TPN = OUT / CPT;      // threads per node
    constexpr int NPB = 256 / TPN;      // nodes per block
    __shared__ __align__(16) float sW[IN * OUT];
    __shared__ float sB[OUT];
    __shared__ float sH[NPB * IN];
    const float* __restrict__ in  = inB  ? g_bufB : g_bufA;
    float*       __restrict__ out = outB ? g_bufB : g_bufA;
    int tid = threadIdx.x;
    for (int i = tid; i < IN * OUT; i += 256) sW[i] = W[i];
    if (tid < OUT) sB[tid] = bias ? bias[tid] : 0.f;
    int base = blockIdx.x * NPB;
    for (int i = tid; i < NPB * IN; i += 256) {
        int nd = i / IN, k = i % IN;
        int node = base + nd;
        sH[i] = (node < N_NODES) ? in[(size_t)node * IN + k] : 0.f;
    }
    __syncthreads();
    int nd = tid / TPN, cg = tid % TPN;
    int node = base + nd;
    if (node >= N_NODES) return;
    float acc[CPT];
    #pragma unroll
    for (int j = 0; j < CPT; j++) acc[j] = sB[cg * CPT + j];
    const float* hrow = &sH[nd * IN];
    #pragma unroll 4
    for (int k = 0; k < IN; k++) {
        float a = hrow[k];
        const float4* wp = reinterpret_cast<const float4*>(sW + k * OUT + cg * CPT);
        #pragma unroll
        for (int q = 0; q < CPT / 4; q++) {
            float4 wv = wp[q];
            acc[q*4+0] = fmaf(a, wv.x, acc[q*4+0]);
            acc[q*4+1] = fmaf(a, wv.y, acc[q*4+1]);
            acc[q*4+2] = fmaf(a, wv.z, acc[q*4+2]);
            acc[q*4+3] = fmaf(a, wv.w, acc[q*4+3]);
        }
    }
    float* op = out + (size_t)node * OUT + cg * CPT;
    #pragma unroll
    for (int q = 0; q < CPT / 4; q++) {
        float4 o;
        o.x = ACT ? fmaxf(acc[q*4+0], 0.f) : acc[q*4+0];
        o.y = ACT ? fmaxf(acc[q*4+1], 0.f) : acc[q*4+1];
        o.z = ACT ? fmaxf(acc[q*4+2], 0.f) : acc[q*4+2];
        o.w = ACT ? fmaxf(acc[q*4+3], 0.f) : acc[q*4+3];
        *(float4*)(op + q * 4) = o;
    }
}

// ---------------------------------------------------------------- pooling + MLP

// batch is sorted: warp sweeps 64 consecutive nodes, accumulating in registers
// and flushing with atomics only on graph-id changes (few flushes per warp).
__global__ void pool_kernel(const void* __restrict__ batch) {
    int w = (blockIdx.x * blockDim.x + threadIdx.x) >> 5;
    int lane = threadIdx.x & 31;
    const int NPW = 64;
    int start = w * NPW;
    if (start >= N_NODES) return;
    int end = min(start + NPW, N_NODES);
    int is64 = g_is64;
    int c = lane * 2;
    float ax = 0.f, ay = 0.f;
    int curg = -1, cnt = 0;
    for (int i = start; i < end; i++) {
        int g = is64 ? (int)((const long long*)batch)[i] : ((const int*)batch)[i];
        if (g != curg) {
            if (curg >= 0) {
                atomicAdd(&g_psum[curg * 64 + c],     ax);
                atomicAdd(&g_psum[curg * 64 + c + 1], ay);
                if (lane == 0) atomicAdd(&g_pcnt[curg], cnt);
            }
            curg = g; ax = 0.f; ay = 0.f; cnt = 0;
        }
        float2 v = *(const float2*)(g_bufB + (size_t)i * 64 + c);
        ax += v.x; ay += v.y; cnt++;
    }
    if (curg >= 0) {
        atomicAdd(&g_psum[curg * 64 + c],     ax);
        atomicAdd(&g_psum[curg * 64 + c + 1], ay);
        if (lane == 0) atomicAdd(&g_pcnt[curg], cnt);
    }
}

__global__ void mlp_kernel(const float* __restrict__ Wl1, const float* __restrict__ bl1,
                           const float* __restrict__ Wl2, const float* __restrict__ bl2,
                           float* __restrict__ out) {
    __shared__ float sW1[64 * 32];
    __shared__ float sb1[32];
    __shared__ float sW2[32];
    __shared__ float sb2;
    int tid = threadIdx.x;
    for (int i = tid; i < 64 * 32; i += 256) sW1[i] = Wl1[i];
    if (tid < 32) { sb1[tid] = bl1[tid]; sW2[tid] = Wl2[tid]; }
    if (tid == 0) sb2 = bl2[0];
    __syncthreads();
    float inv = 1.0f / fmaxf((float)g_pcnt[tid], 1.0f);
    float hid[32];
    #pragma unroll
    for (int cc = 0; cc < 32; cc++) hid[cc] = sb1[cc];
    for (int k = 0; k < 64; k++) {
        float a = g_psum[tid * 64 + k] * inv;
        #pragma unroll
        for (int cc = 0; cc < 32; cc++) hid[cc] = fmaf(a, sW1[k * 32 + cc], hid[cc]);
    }
    float o = sb2;
    #pragma unroll
    for (int cc = 0; cc < 32; cc++) o = fmaf(fmaxf(hid[cc], 0.f), sW2[cc], o);
    out[tid] = o;
}

// ---------------------------------------------------------------- launch

extern "C" void kernel_launch(void* const* d_in, const int* in_sizes, int n_in,
                              void* d_out, int out_size) {
    const float* x    = (const float*)d_in[0];
    const void*  eidx = d_in[1];
    const void*  batch= d_in[2];
    const float* W1   = (const float*)d_in[3];
    const float* b1   = (const float*)d_in[4];
    const float* W2   = (const float*)d_in[5];
    const float* b2   = (const float*)d_in[6];
    const float* W3   = (const float*)d_in[7];
    const float* b3   = (const float*)d_in[8];
    const float* Wl1  = (const float*)d_in[9];
    const float* bl1  = (const float*)d_in[10];
    const float* Wl2  = (const float*)d_in[11];
    const float* bl2  = (const float*)d_in[12];
    float* out = (float*)d_out;

    const int warpGrid = (N_NODES * 32 + 255) / 256;

    zero_kernel   <<<(N_NODES + 255) / 256, 256>>>();
    detect_kernel <<<1, 32>>>((const int*)eidx);
    convert_kernel<<<(N_EDGES + 255) / 256, 256>>>(eidx);
    scan1_kernel  <<<SCAN_BLOCKS, SCAN_CHUNK>>>();
    scan2_kernel  <<<1, 32>>>();
    scan3_kernel  <<<(N_NODES + 1 + 255) / 256, 256>>>();
    fill_kernel   <<<(N_EDGES + 255) / 256, 256>>>();

    // Layer 1: aggregate x (8-d), then GEMM 8->64 (+b1, relu)
    aggX_kernel<<<warpGrid, 256>>>(x);
    gemm_kernel<8, 64, 8, true><<<(N_NODES + 31) / 32, 256>>>(0, W1, b1, 1);
    // Layer 2: aggregate h1 (64-d), then GEMM 64->128 (+b2, relu)
    agg64_kernel<false><<<warpGrid, 256>>>(1, 0, nullptr);
    gemm_kernel<64, 128, 8, true><<<(N_NODES + 15) / 16, 256>>>(0, W2, b2, 1);
    // Layer 3: GEMM 128->64 first, then aggregate (+b3, relu)
    gemm_kernel<128, 64, 4, false><<<(N_NODES + 15) / 16, 256>>>(1, W3, nullptr, 0);
    agg64_kernel<true><<<warpGrid, 256>>>(0, 1, b3);

    pool_kernel<<<(((N_NODES + 63) / 64) * 32 + 255) / 256, 256>>>(batch);
    mlp_kernel<<<1, 256>>>(Wl1, bl1, Wl2, bl2, out);
}